// round 9
// baseline (speedup 1.0000x reference)
#include <cuda_runtime.h>
#include <cuda_fp16.h>
#include <cstdint>

#define NUM_USERS 100000
#define NUM_ITEMS 50000
#define N_NODES   150000
#define EMB_D     64
#define NUM_EDGES 2000000
#define N_DIRECTED (2 * NUM_EDGES)               // 4M real adjacency entries
#define N_PAD (N_DIRECTED + 3 * N_NODES)         // padded upper bound (4.45M)
#define N_PAD4 ((N_PAD + 3) / 4)

#define N_ROWH2  ((N_NODES + 1) * (EMB_D / 2))   // +1 dummy zero row
#define SCAN_TILE 1024
#define N_TILES ((N_NODES + SCAN_TILE - 1) / SCAN_TILE)  // 147

// Scratch (device globals; no allocation allowed).
// Node embeddings fp16: one row = 64 halfs = 128B = one L2 line.
__device__ __half2 g_buf0h[N_ROWH2];
__device__ __half2 g_buf1h[N_ROWH2];
__device__ int     g_deg[N_NODES];
__device__ int     g_off[N_NODES];               // padded offsets
__device__ int     g_cursor[N_NODES];
__device__ int     g_tilesum[N_TILES];
__device__ uint4   g_adj4[N_PAD4];               // adjacency, 16B-aligned

// ---------------------------------------------------------------------------
// init: buf0h = half(concat(user, item)); deg = 0; dummy rows zeroed.
// ---------------------------------------------------------------------------
__global__ void init_kernel(const float4* __restrict__ user4,
                            const float4* __restrict__ item4) {
    const int total4 = N_NODES * (EMB_D / 4);      // 2.4M
    const int user4n = NUM_USERS * (EMB_D / 4);    // 1.6M
    int i = blockIdx.x * blockDim.x + threadIdx.x;
    if (i < total4) {
        float4 v = (i < user4n) ? user4[i] : item4[i - user4n];
        g_buf0h[2 * i + 0] = __floats2half2_rn(v.x, v.y);
        g_buf0h[2 * i + 1] = __floats2half2_rn(v.z, v.w);
    }
    if (i < N_NODES) g_deg[i] = 0;
    if (i < EMB_D / 2) {                           // zero dummy row N_NODES
        g_buf0h[(size_t)N_NODES * 32 + i] = __floats2half2_rn(0.f, 0.f);
        g_buf1h[(size_t)N_NODES * 32 + i] = __floats2half2_rn(0.f, 0.f);
    }
}

// degree histogram over both edge endpoints
__global__ void hist_kernel(const int* __restrict__ erow,
                            const int* __restrict__ ecol) {
    int e = blockIdx.x * blockDim.x + threadIdx.x;
    if (e >= NUM_EDGES) return;
    atomicAdd(&g_deg[erow[e]], 1);
    atomicAdd(&g_deg[ecol[e]], 1);
}

// exclusive scan of PADDED degrees, phase A: per-tile scan + tile sums
__global__ void scanA_kernel() {
    __shared__ int sh[SCAN_TILE];
    int t = threadIdx.x;
    int gid = blockIdx.x * SCAN_TILE + t;
    int v = (gid < N_NODES) ? ((g_deg[gid] + 3) & ~3) : 0;
    sh[t] = v;
    __syncthreads();
    for (int ofs = 1; ofs < SCAN_TILE; ofs <<= 1) {
        int x = (t >= ofs) ? sh[t - ofs] : 0;
        __syncthreads();
        sh[t] += x;
        __syncthreads();
    }
    int incl = sh[t];
    if (gid < N_NODES) g_off[gid] = incl - v;
    if (t == SCAN_TILE - 1) g_tilesum[blockIdx.x] = incl;
}

// phase B: exclusive scan of tile sums
__global__ void scanB_kernel() {
    __shared__ int sh[256];
    int t = threadIdx.x;
    int v = (t < N_TILES) ? g_tilesum[t] : 0;
    sh[t] = v;
    __syncthreads();
    for (int ofs = 1; ofs < 256; ofs <<= 1) {
        int x = (t >= ofs) ? sh[t - ofs] : 0;
        __syncthreads();
        sh[t] += x;
        __syncthreads();
    }
    if (t < N_TILES) g_tilesum[t] = sh[t] - v;
}

// phase C: add tile base, init cursors, write dummy padding entries
__global__ void scanC_kernel() {
    int gid = blockIdx.x * blockDim.x + threadIdx.x;
    if (gid >= N_NODES) return;
    int o = g_off[gid] + g_tilesum[gid / SCAN_TILE];
    g_off[gid] = o;
    g_cursor[gid] = o;
    int d  = g_deg[gid];
    int dp = (d + 3) & ~3;
    int* adj = reinterpret_cast<int*>(g_adj4);
    for (int p = d; p < dp; p++) adj[o + p] = N_NODES;   // dummy zero row
}

// CSR fill: adjacency of both directions
__global__ void fill_kernel(const int* __restrict__ erow,
                            const int* __restrict__ ecol) {
    int e = blockIdx.x * blockDim.x + threadIdx.x;
    if (e >= NUM_EDGES) return;
    int r = erow[e], c = ecol[e];
    int* adj = reinterpret_cast<int*>(g_adj4);
    adj[atomicAdd(&g_cursor[r], 1)] = c;
    adj[atomicAdd(&g_cursor[c], 1)] = r;
}

// ---------------------------------------------------------------------------
// Packed pull: one warp per node; each gather LDG.128 fetches FOUR neighbor
// rows (quarter-warp per neighbor, 8 lanes x 16B = one 128B fp16 row).
// Adjacency read as one uniform int4 per 4 neighbors. fp32 accumulation in
// acc[8] (lane owns cols sub*8..sub*8+7 for its quarter's neighbors);
// cross-quarter combine via shfl_xor(8), shfl_xor(16).
// ---------------------------------------------------------------------------
__device__ __forceinline__ void pull_accum(const __half2* __restrict__ src,
                                           int start, int d, int lane,
                                           float acc[8]) {
    const uint4* __restrict__ adj4 =
        reinterpret_cast<const uint4*>(g_adj4) + (start >> 2);
    int n4 = (d + 3) >> 2;
    int q   = lane >> 3;      // which neighbor of the group
    int sub = lane & 7;       // 16B chunk within the row

    const char* base = reinterpret_cast<const char*>(src);

    int j = 0;
    for (; j + 8 <= n4; j += 8) {
#pragma unroll
        for (int k = 0; k < 8; k++) {
            uint4 av = adj4[j + k];                       // uniform 16B load
            int u = (q == 0) ? (int)av.x : (q == 1) ? (int)av.y
                  : (q == 2) ? (int)av.z : (int)av.w;
            uint4 row = *reinterpret_cast<const uint4*>(
                base + (size_t)u * 128 + sub * 16);
            const __half2* h = reinterpret_cast<const __half2*>(&row);
            float2 f0 = __half22float2(h[0]);
            float2 f1 = __half22float2(h[1]);
            float2 f2 = __half22float2(h[2]);
            float2 f3 = __half22float2(h[3]);
            acc[0] += f0.x; acc[1] += f0.y;
            acc[2] += f1.x; acc[3] += f1.y;
            acc[4] += f2.x; acc[5] += f2.y;
            acc[6] += f3.x; acc[7] += f3.y;
        }
    }
    for (; j < n4; j++) {
        uint4 av = adj4[j];
        int u = (q == 0) ? (int)av.x : (q == 1) ? (int)av.y
              : (q == 2) ? (int)av.z : (int)av.w;
        uint4 row = *reinterpret_cast<const uint4*>(
            base + (size_t)u * 128 + sub * 16);
        const __half2* h = reinterpret_cast<const __half2*>(&row);
        float2 f0 = __half22float2(h[0]);
        float2 f1 = __half22float2(h[1]);
        float2 f2 = __half22float2(h[2]);
        float2 f3 = __half22float2(h[3]);
        acc[0] += f0.x; acc[1] += f0.y;
        acc[2] += f1.x; acc[3] += f1.y;
        acc[4] += f2.x; acc[5] += f2.y;
        acc[6] += f3.x; acc[7] += f3.y;
    }

    // combine the four quarter-warp partial sums
#pragma unroll
    for (int i = 0; i < 8; i++) {
        acc[i] += __shfl_xor_sync(0xFFFFFFFFu, acc[i], 8);
        acc[i] += __shfl_xor_sync(0xFFFFFFFFu, acc[i], 16);
    }
}

// pull layer 1: buf1h[v] = half(0.5 * sum buf0h[adj])
__global__ void pull1_kernel() {
    int gwarp = (blockIdx.x * blockDim.x + threadIdx.x) >> 5;
    if (gwarp >= N_NODES) return;
    int lane = threadIdx.x & 31;
    float acc[8] = {0.f, 0.f, 0.f, 0.f, 0.f, 0.f, 0.f, 0.f};
    pull_accum(g_buf0h, g_off[gwarp], g_deg[gwarp], lane, acc);
    if (lane < 8) {                 // 8 lanes x 16B cover the 128B row
        uint4 o;
        __half2 h0 = __floats2half2_rn(0.5f * acc[0], 0.5f * acc[1]);
        __half2 h1 = __floats2half2_rn(0.5f * acc[2], 0.5f * acc[3]);
        __half2 h2 = __floats2half2_rn(0.5f * acc[4], 0.5f * acc[5]);
        __half2 h3 = __floats2half2_rn(0.5f * acc[6], 0.5f * acc[7]);
        o.x = *reinterpret_cast<unsigned*>(&h0);
        o.y = *reinterpret_cast<unsigned*>(&h1);
        o.z = *reinterpret_cast<unsigned*>(&h2);
        o.w = *reinterpret_cast<unsigned*>(&h3);
        *reinterpret_cast<uint4*>(
            reinterpret_cast<char*>(g_buf1h) + (size_t)gwarp * 128 + lane * 16) = o;
    }
}

// pull layer 2: out[v] = 0.5 * sum buf1h[adj]  (f32 output)
__global__ void pull2_kernel(float* __restrict__ out) {
    int gwarp = (blockIdx.x * blockDim.x + threadIdx.x) >> 5;
    if (gwarp >= N_NODES) return;
    int lane = threadIdx.x & 31;
    float acc[8] = {0.f, 0.f, 0.f, 0.f, 0.f, 0.f, 0.f, 0.f};
    pull_accum(g_buf1h, g_off[gwarp], g_deg[gwarp], lane, acc);
    if (lane < 8) {                 // 8 lanes x 32B cover the 256B f32 row
        float* dp = out + (size_t)gwarp * EMB_D + lane * 8;
        float4 a = make_float4(0.5f * acc[0], 0.5f * acc[1],
                               0.5f * acc[2], 0.5f * acc[3]);
        float4 b = make_float4(0.5f * acc[4], 0.5f * acc[5],
                               0.5f * acc[6], 0.5f * acc[7]);
        *reinterpret_cast<float4*>(dp)     = a;
        *reinterpret_cast<float4*>(dp + 4) = b;
    }
}

// ---------------------------------------------------------------------------
extern "C" void kernel_launch(void* const* d_in, const int* in_sizes, int n_in,
                              void* d_out, int out_size) {
    const int*   edge_index = (const int*)d_in[0];   // [2, E] int32
    const float* user_emb   = (const float*)d_in[1];
    const float* item_emb   = (const float*)d_in[2];
    float*       out        = (float*)d_out;

    const int* erow = edge_index;
    const int* ecol = edge_index + NUM_EDGES;

    // init (convert-copy concat + zero degrees + dummy rows)
    {
        const int total4 = N_NODES * (EMB_D / 4);
        init_kernel<<<(total4 + 255) / 256, 256>>>(
            (const float4*)user_emb, (const float4*)item_emb);
    }

    // CSR build (padded to multiples of 4 per node)
    hist_kernel<<<(NUM_EDGES + 255) / 256, 256>>>(erow, ecol);
    scanA_kernel<<<N_TILES, SCAN_TILE>>>();
    scanB_kernel<<<1, 256>>>();
    scanC_kernel<<<(N_NODES + 255) / 256, 256>>>();
    fill_kernel<<<(NUM_EDGES + 255) / 256, 256>>>(erow, ecol);

    // two pull layers (warp per node, 4 neighbors per gather LDG)
    {
        long long total_threads = (long long)N_NODES * 32;
        int threads = 256;
        int blocks  = (int)((total_threads + threads - 1) / threads);
        pull1_kernel<<<blocks, threads>>>();
        pull2_kernel<<<blocks, threads>>>(out);
    }
}